// round 12
// baseline (speedup 1.0000x reference)
#include <cuda_runtime.h>
#include <cuda_bf16.h>
#include <math.h>
#include <cstdint>

// ---------------------------------------------------------------------------
// STN. R10: conv1 via warp-level mma.sync.m16n8k16 (bf16 hi/lo split, 3
// passes) — baseline-PTX legal on compute_103 (tcgen05 is NOT: harness
// compiles через compute_103 PTX). conv2/conv3 FFMA2 SIMT, rest unchanged.
// ---------------------------------------------------------------------------

__device__ __align__(16) float g_C1[16u * 254 * 254 * 16];
__device__ __align__(16) float g_P1[16u * 127 * 127 * 16];
__device__ __align__(16) float g_P2[16u * 62 * 62 * 32];
__device__ __align__(16) float g_part[16][8][32];
__device__ __align__(16) float g_theta[16 * 6];

__constant__ float c_W2[3 * 3 * 16 * 32];
__constant__ float c_b2[32];

// ---- bf16 mma.sync (HMMA fallback path; no 'a'-feature required) ----------
__device__ __forceinline__ void mma16816(float* d, const uint32_t* a,
                                         const uint32_t* b) {
    asm volatile(
        "mma.sync.aligned.m16n8k16.row.col.f32.bf16.bf16.f32 "
        "{%0,%1,%2,%3}, {%4,%5,%6,%7}, {%8,%9}, {%0,%1,%2,%3};"
        : "+f"(d[0]), "+f"(d[1]), "+f"(d[2]), "+f"(d[3])
        : "r"(a[0]), "r"(a[1]), "r"(a[2]), "r"(a[3]), "r"(b[0]), "r"(b[1]));
}

// ---------------------------------------------------------------------------
// conv1: x(16,256,256,32)*W1+b1 -> relu -> g_C1(16,254,254,16)  [tensor]
// CTA = (col-half, conv row r, batch). 8 warps x 16 pixels, N=16 couts,
// K = 9 taps x 32 ci, bf16 hi/lo (hh+hl+lh). smem: 72B-padded [px][ci] rows.
// ---------------------------------------------------------------------------
static constexpr int C1_ROWB = 130 * 72;          // 9360 per input row
static constexpr int C1_XH   = 0;
static constexpr int C1_XL   = 3 * C1_ROWB;        // 28080
static constexpr int C1_WH   = 2 * C1_XL;          // 56160
static constexpr int C1_WL   = C1_WH + 9 * 16 * 72;  // 66528
static constexpr int C1_SMEM = C1_WL + 9 * 16 * 72;  // 76896

__global__ void __launch_bounds__(256) conv1m_kernel(
    const float* __restrict__ x, const float* __restrict__ W,
    const float* __restrict__ bias)
{
    extern __shared__ char smem[];
    char* sXh = smem + C1_XH;
    char* sXl = smem + C1_XL;
    char* sWh = smem + C1_WH;
    char* sWl = smem + C1_WL;

    const int t = threadIdx.x;
    const int b = blockIdx.z, r = blockIdx.y;
    const int c0 = blockIdx.x * 126;

    // weights: W[tap][ci][co] -> sW[tap][co][ci] (72B-padded), hi/lo
    for (int i = t; i < 4608; i += 256) {
        const int tap = i >> 9, rem = i & 511, ci = rem >> 4, co = rem & 15;
        const float v = W[i];
        const __nv_bfloat16 h = __float2bfloat16(v);
        const __nv_bfloat16 l = __float2bfloat16(v - __bfloat162float(h));
        const int off = (tap * 16 + co) * 72 + ci * 2;
        *(__nv_bfloat16*)(sWh + off) = h;
        *(__nv_bfloat16*)(sWl + off) = l;
    }
    // input rows r..r+2, cols c0..c0+129: fp32 -> bf16 hi/lo, [px][ci] 72B
    for (int i = t; i < 3 * 130 * 8; i += 256) {
        const int q = i & 7, cc = (i >> 3) % 130, rr = (i >> 3) / 130;
        const float4 v = *(const float4*)(
            x + (((size_t)(b * 256 + r + rr) * 256) + c0 + cc) * 32 + q * 4);
        __nv_bfloat162 h0, h1, l0, l1;
        h0.x = __float2bfloat16(v.x); h0.y = __float2bfloat16(v.y);
        h1.x = __float2bfloat16(v.z); h1.y = __float2bfloat16(v.w);
        l0.x = __float2bfloat16(v.x - __bfloat162float(h0.x));
        l0.y = __float2bfloat16(v.y - __bfloat162float(h0.y));
        l1.x = __float2bfloat16(v.z - __bfloat162float(h1.x));
        l1.y = __float2bfloat16(v.w - __bfloat162float(h1.y));
        const int off = (rr * 130 + cc) * 72 + q * 8;
        *(uint32_t*)(sXh + off)     = *(uint32_t*)&h0;
        *(uint32_t*)(sXh + off + 4) = *(uint32_t*)&h1;
        *(uint32_t*)(sXl + off)     = *(uint32_t*)&l0;
        *(uint32_t*)(sXl + off + 4) = *(uint32_t*)&l1;
    }
    __syncthreads();

    const int w = t >> 5, lane = t & 31;
    const int g = lane >> 2, tq = lane & 3;
    const int px = w * 16 + g;           // A-row pixel (this thread's d0/d1)
    const int tq4 = tq * 4;

    float dhh[2][4], dhl[2][4], dlh[2][4];
#pragma unroll
    for (int h = 0; h < 2; ++h)
#pragma unroll
        for (int j = 0; j < 4; ++j) { dhh[h][j] = 0.f; dhl[h][j] = 0.f; dlh[h][j] = 0.f; }

#pragma unroll
    for (int ky = 0; ky < 3; ++ky) {
#pragma unroll
        for (int kx = 0; kx < 3; ++kx) {
            const int tap = ky * 3 + kx;
            const char* ra_h = sXh + ky * C1_ROWB + (px + kx) * 72;
            const char* ra_l = sXl + ky * C1_ROWB + (px + kx) * 72;
#pragma unroll
            for (int ks = 0; ks < 2; ++ks) {
                const int ao = ks * 32 + tq4;
                uint32_t ah[4], al[4];
                ah[0] = *(const uint32_t*)(ra_h + ao);
                ah[1] = *(const uint32_t*)(ra_h + 8 * 72 + ao);
                ah[2] = *(const uint32_t*)(ra_h + ao + 16);
                ah[3] = *(const uint32_t*)(ra_h + 8 * 72 + ao + 16);
                al[0] = *(const uint32_t*)(ra_l + ao);
                al[1] = *(const uint32_t*)(ra_l + 8 * 72 + ao);
                al[2] = *(const uint32_t*)(ra_l + ao + 16);
                al[3] = *(const uint32_t*)(ra_l + 8 * 72 + ao + 16);
#pragma unroll
                for (int h = 0; h < 2; ++h) {
                    const int bo = (tap * 16 + 8 * h + g) * 72 + ks * 32 + tq4;
                    uint32_t bh[2], bl[2];
                    bh[0] = *(const uint32_t*)(sWh + bo);
                    bh[1] = *(const uint32_t*)(sWh + bo + 16);
                    bl[0] = *(const uint32_t*)(sWl + bo);
                    bl[1] = *(const uint32_t*)(sWl + bo + 16);
                    mma16816(dhh[h], ah, bh);
                    mma16816(dhl[h], ah, bl);
                    mma16816(dlh[h], al, bh);
                }
            }
        }
    }

    // epilogue: bias + relu -> g_C1. Thread owns pixels px, px+8;
    // couts 8h + tq*2, +1.
    float* o = g_C1 + ((size_t)(b * 254 + r) * 254 + (c0 + px)) * 16;
#pragma unroll
    for (int h = 0; h < 2; ++h) {
        const int co = 8 * h + tq * 2;
        const float bb0 = bias[co], bb1 = bias[co + 1];
        float v0 = fmaxf(dhh[h][0] + (dhl[h][0] + dlh[h][0]) + bb0, 0.f);
        float v1 = fmaxf(dhh[h][1] + (dhl[h][1] + dlh[h][1]) + bb1, 0.f);
        float v2 = fmaxf(dhh[h][2] + (dhl[h][2] + dlh[h][2]) + bb0, 0.f);
        float v3 = fmaxf(dhh[h][3] + (dhl[h][3] + dlh[h][3]) + bb1, 0.f);
        *(float2*)(o + co)       = make_float2(v0, v1);
        *(float2*)(o + 128 + co) = make_float2(v2, v3);   // pixel px+8
    }
}

// ===================== pool: g_C1 -> g_P1 ==================================
__global__ __launch_bounds__(256) void pool1_kernel()
{
    const int idx = blockIdx.x * 256 + threadIdx.x;
    if (idx >= 16 * 127 * 127 * 2) return;
    const int h = idx & 1;
    const int pix = idx >> 1;
    const int q = pix % 127, tmp = pix / 127;
    const int p = tmp % 127, b = tmp / 127;
    const float* base = g_C1 + ((size_t)(b * 254 + 2 * p) * 254 + 2 * q) * 16 + 8 * h;
    float* op = g_P1 + ((size_t)(b * 127 + p) * 127 + q) * 16 + 8 * h;
#pragma unroll
    for (int w = 0; w < 2; ++w) {
        float4 a = ((const float4*)(base))[w];
        float4 c = ((const float4*)(base + 16))[w];
        float4 e = ((const float4*)(base + 254 * 16))[w];
        float4 f = ((const float4*)(base + 254 * 16 + 16))[w];
        float4 o;
        o.x = fmaxf(fmaxf(a.x, c.x), fmaxf(e.x, f.x));
        o.y = fmaxf(fmaxf(a.y, c.y), fmaxf(e.y, f.y));
        o.z = fmaxf(fmaxf(a.z, c.z), fmaxf(e.z, f.z));
        o.w = fmaxf(fmaxf(a.w, c.w), fmaxf(e.w, f.w));
        ((float4*)op)[w] = o;
    }
}

// ==================== FFMA2 SIMT path (conv2/conv3) ========================
__device__ __forceinline__ unsigned long long pack2(float v) {
    unsigned long long r;
    asm("mov.b64 %0, {%1, %1};" : "=l"(r) : "r"(__float_as_uint(v)));
    return r;
}
__device__ __forceinline__ void ffma2(unsigned long long& a, unsigned long long v,
                                      unsigned long long w) {
    asm("fma.rn.f32x2 %0, %1, %2, %0;" : "+l"(a) : "l"(v), "l"(w));
}
__device__ __forceinline__ float2 unpack2(unsigned long long a) {
    float lo, hi;
    asm("mov.b64 {%0, %1}, %2;" : "=f"(lo), "=f"(hi) : "l"(a));
    return make_float2(lo, hi);
}

__global__ __launch_bounds__(256, 2) void conv2_kernel()
{
    __shared__ __align__(16) float sIn[4][18][36];
    const int b = blockIdx.z, by = blockIdx.y, bx = blockIdx.x;
    const int t = threadIdx.x;
    const int grp = t >> 6, slot = t & 63, py = slot >> 3, pxi = slot & 7;
    const int r0 = by * 16, c0 = bx * 32;

    unsigned long long acc[2][4][4];
#pragma unroll
    for (int dr = 0; dr < 2; ++dr)
#pragma unroll
        for (int dc = 0; dc < 4; ++dc)
#pragma unroll
            for (int j = 0; j < 4; ++j) acc[dr][dc][j] = 0ULL;

    for (int cc = 0; cc < 4; ++cc) {
        __syncthreads();
        for (int i = t; i < 18 * 34; i += 256) {
            int rr = i / 34, c = i - 34 * (i / 34);
            int gr = r0 + rr, gc = c0 + c;
            float4 v = make_float4(0.f, 0.f, 0.f, 0.f);
            if (gr < 127 && gc < 127)
                v = *(const float4*)(g_P1 + (((size_t)(b * 127 + gr) * 127 + gc) * 16 + cc * 4));
            sIn[0][rr][c] = v.x; sIn[1][rr][c] = v.y;
            sIn[2][rr][c] = v.z; sIn[3][rr][c] = v.w;
        }
        __syncthreads();
#pragma unroll
        for (int ci = 0; ci < 4; ++ci) {
            float v[4][6];
#pragma unroll
            for (int dr = 0; dr < 4; ++dr) {
                const float* row = &sIn[ci][2 * py + dr][4 * pxi];
                float4 f = *(const float4*)row;
                float2 g = *(const float2*)(row + 4);
                v[dr][0] = f.x; v[dr][1] = f.y; v[dr][2] = f.z;
                v[dr][3] = f.w; v[dr][4] = g.x; v[dr][5] = g.y;
            }
#pragma unroll
            for (int ky = 0; ky < 3; ++ky)
#pragma unroll
                for (int kx = 0; kx < 3; ++kx) {
                    const ulonglong2* wp = (const ulonglong2*)
                        &c_W2[(((ky * 3 + kx) * 16) + cc * 4 + ci) * 32 + 8 * grp];
                    ulonglong2 qa = wp[0], qb = wp[1];
#pragma unroll
                    for (int dr = 0; dr < 2; ++dr)
#pragma unroll
                        for (int dc = 0; dc < 4; ++dc) {
                            unsigned long long vv = pack2(v[ky + dr][kx + dc]);
                            ffma2(acc[dr][dc][0], vv, qa.x);
                            ffma2(acc[dr][dc][1], vv, qa.y);
                            ffma2(acc[dr][dc][2], vv, qb.x);
                            ffma2(acc[dr][dc][3], vv, qb.y);
                        }
                }
        }
    }

    const int ph = by * 8 + py;
#pragma unroll
    for (int s = 0; s < 2; ++s) {
        const int pw = bx * 16 + 2 * pxi + s;
        if (ph < 62 && pw < 62) {
            float* op = g_P2 + ((size_t)(b * 62 + ph) * 62 + pw) * 32 + 8 * grp;
#pragma unroll
            for (int j = 0; j < 4; ++j) {
                float2 a0 = unpack2(acc[0][2 * s][j]);
                float2 a1 = unpack2(acc[0][2 * s + 1][j]);
                float2 a2 = unpack2(acc[1][2 * s][j]);
                float2 a3 = unpack2(acc[1][2 * s + 1][j]);
                float mlo = fmaxf(fmaxf(a0.x, a1.x), fmaxf(a2.x, a3.x));
                float mhi = fmaxf(fmaxf(a0.y, a1.y), fmaxf(a2.y, a3.y));
                op[2 * j]     = fmaxf(mlo + c_b2[8 * grp + 2 * j], 0.f);
                op[2 * j + 1] = fmaxf(mhi + c_b2[8 * grp + 2 * j + 1], 0.f);
            }
        }
    }
}

__global__ __launch_bounds__(256, 2) void conv3_kernel(
    const float* __restrict__ W, const float* __restrict__ bias)
{
    __shared__ __align__(16) float sIn[4][18][36];
    __shared__ __align__(16) float sW[9 * 4 * 32];
    __shared__ float sRed[64][32];

    const int b = blockIdx.z, by = blockIdx.y, bx = blockIdx.x;
    const int t = threadIdx.x;
    const int grp = t >> 6, slot = t & 63, py = slot >> 3, pxi = slot & 7;
    const int r0 = by * 16, c0 = bx * 32;

    unsigned long long acc[2][4][4];
#pragma unroll
    for (int dr = 0; dr < 2; ++dr)
#pragma unroll
        for (int dc = 0; dc < 4; ++dc)
#pragma unroll
            for (int j = 0; j < 4; ++j) acc[dr][dc][j] = 0ULL;

    for (int cc = 0; cc < 8; ++cc) {
        __syncthreads();
        for (int i = t; i < 18 * 34; i += 256) {
            int rr = i / 34, c = i - 34 * (i / 34);
            int gr = r0 + rr, gc = c0 + c;
            float4 v = make_float4(0.f, 0.f, 0.f, 0.f);
            if (gr < 62 && gc < 62)
                v = *(const float4*)(g_P2 + (((size_t)(b * 62 + gr) * 62 + gc) * 32 + cc * 4));
            sIn[0][rr][c] = v.x; sIn[1][rr][c] = v.y;
            sIn[2][rr][c] = v.z; sIn[3][rr][c] = v.w;
        }
        for (int i = t; i < 1152; i += 256) {
            int kk = i >> 7, rem = i & 127;
            int ci = rem >> 5, co = rem & 31;
            sW[i] = W[((kk * 32) + cc * 4 + ci) * 32 + co];
        }
        __syncthreads();
#pragma unroll
        for (int ci = 0; ci < 4; ++ci) {
            float v[4][6];
#pragma unroll
            for (int dr = 0; dr < 4; ++dr) {
                const float* row = &sIn[ci][2 * py + dr][4 * pxi];
                float4 f = *(const float4*)row;
                float2 g = *(const float2*)(row + 4);
                v[dr][0] = f.x; v[dr][1] = f.y; v[dr][2] = f.z;
                v[dr][3] = f.w; v[dr][4] = g.x; v[dr][5] = g.y;
            }
#pragma unroll
            for (int ky = 0; ky < 3; ++ky)
#pragma unroll
                for (int kx = 0; kx < 3; ++kx) {
                    const ulonglong2* wp = (const ulonglong2*)
                        &sW[((ky * 3 + kx) * 4 + ci) * 32 + 8 * grp];
                    ulonglong2 qa = wp[0], qb = wp[1];
#pragma unroll
                    for (int dr = 0; dr < 2; ++dr)
#pragma unroll
                        for (int dc = 0; dc < 4; ++dc) {
                            unsigned long long vv = pack2(v[ky + dr][kx + dc]);
                            ffma2(acc[dr][dc][0], vv, qa.x);
                            ffma2(acc[dr][dc][1], vv, qa.y);
                            ffma2(acc[dr][dc][2], vv, qb.x);
                            ffma2(acc[dr][dc][3], vv, qb.y);
                        }
                }
        }
    }

    const int ph = by * 8 + py;
    float csum[8];
#pragma unroll
    for (int j = 0; j < 8; ++j) csum[j] = 0.f;
#pragma unroll
    for (int s = 0; s < 2; ++s) {
        const int pw = bx * 16 + 2 * pxi + s;
        const bool valid = (ph < 30) && (pw < 30);
#pragma unroll
        for (int j = 0; j < 4; ++j) {
            float2 a0 = unpack2(acc[0][2 * s][j]);
            float2 a1 = unpack2(acc[0][2 * s + 1][j]);
            float2 a2 = unpack2(acc[1][2 * s][j]);
            float2 a3 = unpack2(acc[1][2 * s + 1][j]);
            float mlo = fmaxf(fmaxf(a0.x, a1.x), fmaxf(a2.x, a3.x));
            float mhi = fmaxf(fmaxf(a0.y, a1.y), fmaxf(a2.y, a3.y));
            float vlo = fmaxf(mlo + bias[8 * grp + 2 * j], 0.f);
            float vhi = fmaxf(mhi + bias[8 * grp + 2 * j + 1], 0.f);
            if (valid) { csum[2 * j] += vlo; csum[2 * j + 1] += vhi; }
        }
    }
    __syncthreads();
#pragma unroll
    for (int j = 0; j < 8; ++j) sRed[slot][8 * grp + j] = csum[j];
    __syncthreads();

    if (t < 32) {
        float s = 0.f;
#pragma unroll
        for (int p = 0; p < 64; ++p) s += sRed[p][t];
        g_part[b][by * 2 + bx][t] = s;
    }
}

// ============================ head / sampler ===============================
__global__ __launch_bounds__(64) void head_kernel(
    const float* __restrict__ D1, const float* __restrict__ db1,
    const float* __restrict__ D2, const float* __restrict__ db2,
    const float* __restrict__ D3, const float* __restrict__ db3)
{
    __shared__ float h0[32], h1[64], h2[32];
    const int b = blockIdx.x, t = threadIdx.x;

    if (t < 32) {
        float s = 0.f;
#pragma unroll
        for (int tile = 0; tile < 8; ++tile) s += g_part[b][tile][t];
        h0[t] = s * (1.f / 900.f);
    }
    __syncthreads();
    {
        float a = db1[t];
#pragma unroll
        for (int k = 0; k < 32; ++k) a = fmaf(h0[k], D1[k * 64 + t], a);
        h1[t] = fmaxf(a, 0.f);
    }
    __syncthreads();
    if (t < 32) {
        float a = db2[t];
#pragma unroll
        for (int k = 0; k < 64; ++k) a = fmaf(h1[k], D2[k * 32 + t], a);
        h2[t] = fmaxf(a, 0.f);
    }
    __syncthreads();
    if (t < 6) {
        float a = db3[t];
#pragma unroll
        for (int k = 0; k < 32; ++k) a = fmaf(h2[k], D3[k * 6 + t], a);
        g_theta[b * 6 + t] = a;
    }
}

__global__ __launch_bounds__(256) void sampler_kernel(
    const float* __restrict__ x, float* __restrict__ out)
{
    __shared__ float th[6];
    const int b = blockIdx.y;
    if (threadIdx.x < 6) th[threadIdx.x] = g_theta[b * 6 + threadIdx.x];
    __syncthreads();

    const int idx = blockIdx.x * 64 + (threadIdx.x >> 2);
    const int c8 = (threadIdx.x & 3) * 8;
    const int i = idx >> 8, j = idx & 255;

    const float xs = -1.f + (float)j * (2.f / 255.f);
    const float ys = -1.f + (float)i * (2.f / 255.f);
    const float xc = th[0] * xs + th[1] * ys + th[2];
    const float yc = th[3] * xs + th[4] * ys + th[5];
    const float xf = 0.5f * ((xc + 1.0f) * 254.0f);
    const float yf = 0.5f * ((yc + 1.0f) * 254.0f);

    int x0 = (int)floorf(xf), x1 = x0 + 1;
    int y0 = (int)floorf(yf), y1 = y0 + 1;
    x0 = min(max(x0, 0), 255); x1 = min(max(x1, 0), 255);
    y0 = min(max(y0, 0), 255); y1 = min(max(y1, 0), 255);

    const float x0f = (float)x0, x1f = (float)x1;
    const float y0f = (float)y0, y1f = (float)y1;
    const float wa = (x1f - xf) * (y1f - yf);
    const float wb = (x1f - xf) * (yf - y0f);
    const float wc = (xf - x0f) * (y1f - yf);
    const float wd = (xf - x0f) * (yf - y0f);

    const float* xb = x + (size_t)b * 256 * 256 * 32;
    const float* pa = xb + ((size_t)(y0 * 256 + x0) * 32 + c8);
    const float* pb = xb + ((size_t)(y1 * 256 + x0) * 32 + c8);
    const float* pc = xb + ((size_t)(y0 * 256 + x1) * 32 + c8);
    const float* pd = xb + ((size_t)(y1 * 256 + x1) * 32 + c8);
    float* po = out + ((size_t)(b * 65536 + idx) * 32 + c8);

#pragma unroll
    for (int h = 0; h < 2; ++h) {
        const float4 Ia = __ldg((const float4*)(pa + 4 * h));
        const float4 Ib = __ldg((const float4*)(pb + 4 * h));
        const float4 Ic = __ldg((const float4*)(pc + 4 * h));
        const float4 Id = __ldg((const float4*)(pd + 4 * h));
        float4 rr;
        rr.x = wa * Ia.x + wb * Ib.x + wc * Ic.x + wd * Id.x;
        rr.y = wa * Ia.y + wb * Ib.y + wc * Ic.y + wd * Id.y;
        rr.z = wa * Ia.z + wb * Ib.z + wc * Ic.z + wd * Id.z;
        rr.w = wa * Ia.w + wb * Ib.w + wc * Ic.w + wd * Id.w;
        *(float4*)(po + 4 * h) = rr;
    }
}

// ---------------------------------------------------------------------------
extern "C" void kernel_launch(void* const* d_in, const int* in_sizes, int n_in,
                              void* d_out, int out_size)
{
    const float* x   = (const float*)d_in[0];
    const float* W1  = (const float*)d_in[1];
    const float* b1  = (const float*)d_in[2];
    const float* W3  = (const float*)d_in[5];
    const float* b3  = (const float*)d_in[6];
    const float* D1  = (const float*)d_in[7];
    const float* db1 = (const float*)d_in[8];
    const float* D2  = (const float*)d_in[9];
    const float* db2 = (const float*)d_in[10];
    const float* D3  = (const float*)d_in[11];
    const float* db3 = (const float*)d_in[12];
    float* out = (float*)d_out;

    cudaMemcpyToSymbolAsync(c_W2, d_in[3], 4608 * sizeof(float), 0,
                            cudaMemcpyDeviceToDevice, 0);
    cudaMemcpyToSymbolAsync(c_b2, d_in[4], 32 * sizeof(float), 0,
                            cudaMemcpyDeviceToDevice, 0);

    cudaFuncSetAttribute(conv1m_kernel,
                         cudaFuncAttributeMaxDynamicSharedMemorySize, C1_SMEM);

    conv1m_kernel<<<dim3(2, 254, 16), 256, C1_SMEM>>>(x, W1, b1);
    pool1_kernel<<<2017, 256>>>();
    conv2_kernel<<<dim3(4, 8, 16), 256>>>();
    conv3_kernel<<<dim3(2, 4, 16), 256>>>(W3, b3);
    head_kernel<<<16, 64>>>(D1, db1, D2, db2, D3, db3);
    sampler_kernel<<<dim3(1024, 16), 256>>>(x, out);
}